// round 1
// baseline (speedup 1.0000x reference)
#include <cuda_runtime.h>
#include <cuda_fp16.h>
#include <cstdint>

// ---------------------------------------------------------------------------
// CondTransport: out = (y_mean + y_var) + z_mean + z_var
//   z = rbf(X, x, l=8).T @ (kXX_inv @ Z)   for mean (DK=64) and var (DK=96)
// Strategy: fp16 tensor-core (mma.sync m16n8k16) everywhere, fp32 accum,
// flash-style fusion of rbf+exp+second GEMM. All scratch in __device__ globals.
// ---------------------------------------------------------------------------

namespace {
constexpr int N_Q     = 8192;
constexpr int N_XR    = 8192;
constexpr int D_OUT   = 32;
constexpr int DK_MEAN = 64;
constexpr int DK_VAR  = 96;
constexpr float VAR_EPS_F = 0.01f;
constexpr float INV_2L2   = 1.0f / 128.0f;   // 1/(2*l*l), l=8
}

// ------------------------- device scratch (no allocs allowed) ---------------
__device__ __half g_Qm[N_Q * DK_MEAN];
__device__ __half g_Qv[N_Q * DK_VAR];
__device__ __half g_Xm[N_XR * DK_MEAN];
__device__ __half g_Xv[N_XR * DK_VAR];
__device__ float  g_qn_m[N_Q];
__device__ float  g_qn_v[N_Q];
__device__ float  g_xn_m[N_XR];
__device__ float  g_xn_v[N_XR];
__device__ __half g_ZTm[D_OUT * N_XR];    // Z transposed [32][8192], fp16
__device__ __half g_ZTv[D_OUT * N_XR];
__device__ float  g_LamFm[N_XR * D_OUT];  // fp32 Lambda accumulators
__device__ float  g_LamFv[N_XR * D_OUT];
__device__ __half g_LamTm[D_OUT * N_XR];  // Lambda transposed [32][8192], fp16
__device__ __half g_LamTv[D_OUT * N_XR];

// ------------------------- mma helper ---------------------------------------
__device__ __forceinline__ void mma16816(float c[4], const uint32_t a[4],
                                         const uint32_t b[2]) {
    asm volatile(
        "mma.sync.aligned.m16n8k16.row.col.f32.f16.f16.f32 "
        "{%0,%1,%2,%3}, {%4,%5,%6,%7}, {%8,%9}, {%0,%1,%2,%3};\n"
        : "+f"(c[0]), "+f"(c[1]), "+f"(c[2]), "+f"(c[3])
        : "r"(a[0]), "r"(a[1]), "r"(a[2]), "r"(a[3]), "r"(b[0]), "r"(b[1]));
}

// ------------------------- prep ---------------------------------------------
// One warp per row (8192 rows). Builds all fp16 operands, fp32 norms,
// transposed fp16 Z, zeroes Lambda accumulators, inits out = y_mean + y_var.
__global__ void prep_kernel(const float* __restrict__ x_mu,
                            const float* __restrict__ y_eta,
                            const float* __restrict__ y_mean,
                            const float* __restrict__ y_var,
                            const float* __restrict__ X_mean,
                            const float* __restrict__ X_var,
                            const float* __restrict__ Z_mean,
                            const float* __restrict__ Z_var,
                            float* __restrict__ out) {
    const int row  = blockIdx.x * 8 + (threadIdx.x >> 5);
    const int lane = threadIdx.x & 31;

    // ---- query-side features: x_mean = [x_mu, ymv], x_var = [x_mu, ef, ymv]
    const float xm  = x_mu[row * 32 + lane];
    const float ymv = y_mean[row * 32 + lane] + y_var[row * 32 + lane];
    const float ef  = VAR_EPS_F * y_eta[(N_Q - 1 - row) * 32 + lane];  // flip axis 0

    g_Qm[row * DK_MEAN + lane]       = __float2half(xm);
    g_Qm[row * DK_MEAN + 32 + lane]  = __float2half(ymv);
    g_Qv[row * DK_VAR + lane]        = __float2half(xm);
    g_Qv[row * DK_VAR + 32 + lane]   = __float2half(ef);
    g_Qv[row * DK_VAR + 64 + lane]   = __float2half(ymv);
    out[row * 32 + lane] = ymv;

    float nm = xm * xm + ymv * ymv;
    float nv = nm + ef * ef;

    // ---- X-side features + norms
    const float a0 = X_mean[row * 64 + lane];
    const float a1 = X_mean[row * 64 + 32 + lane];
    g_Xm[row * 64 + lane]      = __float2half(a0);
    g_Xm[row * 64 + 32 + lane] = __float2half(a1);
    float xnm = a0 * a0 + a1 * a1;

    const float b0 = X_var[row * 96 + lane];
    const float b1 = X_var[row * 96 + 32 + lane];
    const float b2 = X_var[row * 96 + 64 + lane];
    g_Xv[row * 96 + lane]      = __float2half(b0);
    g_Xv[row * 96 + 32 + lane] = __float2half(b1);
    g_Xv[row * 96 + 64 + lane] = __float2half(b2);
    float xnv = b0 * b0 + b1 * b1 + b2 * b2;

    #pragma unroll
    for (int o = 16; o; o >>= 1) {
        nm  += __shfl_xor_sync(0xffffffffu, nm, o);
        nv  += __shfl_xor_sync(0xffffffffu, nv, o);
        xnm += __shfl_xor_sync(0xffffffffu, xnm, o);
        xnv += __shfl_xor_sync(0xffffffffu, xnv, o);
    }
    if (lane == 0) {
        g_qn_m[row] = nm;
        g_qn_v[row] = nv;
        g_xn_m[row] = xnm;
        g_xn_v[row] = xnv;
    }

    // ---- Z transposed fp16, Lambda accumulators zeroed
    g_ZTm[lane * N_XR + row] = __float2half(Z_mean[row * 32 + lane]);
    g_ZTv[lane * N_XR + row] = __float2half(Z_var[row * 32 + lane]);
    g_LamFm[row * 32 + lane] = 0.0f;
    g_LamFv[row * 32 + lane] = 0.0f;
}

// ------------------------- Lambda = kXX_inv @ Z ------------------------------
// M-tile 128 (8 warps x m16), N=32, K split 4-way across blockIdx.y,
// K-tile 64: stream fp32 A, convert to fp16 smem, mma, fp32 atomicAdd out.
template <int PATH>
__global__ void __launch_bounds__(256, 2)
lambda_kernel(const float* __restrict__ A) {
    constexpr int KT = 64;
    constexpr int KCHUNK = N_XR / 4;
    __shared__ __half As[128 * 72];
    __shared__ __half Zs[32 * 72];

    const __half* ZT  = (PATH == 0) ? g_ZTm : g_ZTv;
    float* LamF       = (PATH == 0) ? g_LamFm : g_LamFv;

    const int tid = threadIdx.x, wid = tid >> 5, lane = tid & 31;
    const int m0 = blockIdx.x * 128;
    const int k0 = blockIdx.y * KCHUNK;

    float C[4][4];
    #pragma unroll
    for (int j = 0; j < 4; ++j)
        #pragma unroll
        for (int k = 0; k < 4; ++k) C[j][k] = 0.0f;

    for (int kt = 0; kt < KCHUNK / KT; ++kt) {
        const int kb = k0 + kt * KT;
        __syncthreads();
        // A tile [128 x 64] fp32 -> fp16 smem
        #pragma unroll
        for (int t = tid; t < 128 * 16; t += 256) {
            const int r = t >> 4, s = t & 15;
            float4 v = *(const float4*)(A + (size_t)(m0 + r) * N_XR + kb + s * 4);
            *(__half2*)&As[r * 72 + s * 4]     = __floats2half2_rn(v.x, v.y);
            *(__half2*)&As[r * 72 + s * 4 + 2] = __floats2half2_rn(v.z, v.w);
        }
        {   // Z tile [32 x 64] fp16 (k-contiguous since ZT is [n][k])
            const int r = tid >> 3, s = tid & 7;
            *(uint4*)&Zs[r * 72 + s * 8] = *(const uint4*)(ZT + r * N_XR + kb + s * 8);
        }
        __syncthreads();
        #pragma unroll
        for (int ks = 0; ks < 4; ++ks) {
            uint32_t a[4];
            const __half* ap = &As[(wid * 16 + (lane >> 2)) * 72 + ks * 16 + (lane & 3) * 2];
            a[0] = *(const uint32_t*)ap;
            a[1] = *(const uint32_t*)(ap + 8 * 72);
            a[2] = *(const uint32_t*)(ap + 8);
            a[3] = *(const uint32_t*)(ap + 8 * 72 + 8);
            #pragma unroll
            for (int jb = 0; jb < 4; ++jb) {
                uint32_t b[2];
                const __half* bp = &Zs[(jb * 8 + (lane >> 2)) * 72 + ks * 16 + (lane & 3) * 2];
                b[0] = *(const uint32_t*)bp;
                b[1] = *(const uint32_t*)(bp + 8);
                mma16816(C[jb], a, b);
            }
        }
    }
    const int r = m0 + wid * 16 + (lane >> 2);
    const int c = (lane & 3) * 2;
    #pragma unroll
    for (int jb = 0; jb < 4; ++jb) {
        atomicAdd(&LamF[r * 32 + jb * 8 + c],           C[jb][0]);
        atomicAdd(&LamF[r * 32 + jb * 8 + c + 1],       C[jb][1]);
        atomicAdd(&LamF[(r + 8) * 32 + jb * 8 + c],     C[jb][2]);
        atomicAdd(&LamF[(r + 8) * 32 + jb * 8 + c + 1], C[jb][3]);
    }
}

// ------------------------- Lambda fp32 -> fp16 transposed --------------------
__global__ void lamconvert_kernel() {
    const int idx = blockIdx.x * 256 + threadIdx.x;   // i*32 + j
    const int i = idx >> 5, j = idx & 31;
    g_LamTm[j * N_XR + i] = __float2half(g_LamFm[idx]);
    g_LamTv[j * N_XR + i] = __float2half(g_LamFv[idx]);
}

// ------------------------- fused transport -----------------------------------
// out[q,:] += sum_i exp(-max(|X_i|^2+|x_q|^2-2<X_i,x_q>,0)/128) * Lam[i,:]
// Q-tile 128 (8 warps x m16), i-tile 64, i-range split 4-way across blockIdx.y,
// atomicAdd into out.
template <int PATH>
__global__ void __launch_bounds__(256, 2)
transport_kernel(float* __restrict__ out) {
    constexpr int DK  = (PATH == 0) ? DK_MEAN : DK_VAR;
    constexpr int QT  = 128;
    constexpr int IT  = 64;
    constexpr int LDA = DK + 8;
    constexpr int LDL = IT + 8;
    constexpr int ICHUNK = N_XR / 4;
    constexpr int SEGS = DK / 8;

    __shared__ __half Qs[QT * LDA];
    __shared__ __half Xs[IT * LDA];
    __shared__ __half Ls[D_OUT * LDL];
    __shared__ float  qns[QT];
    __shared__ float  xns[IT];

    const __half* Qh   = (PATH == 0) ? g_Qm : g_Qv;
    const __half* Xh   = (PATH == 0) ? g_Xm : g_Xv;
    const float*  qn   = (PATH == 0) ? g_qn_m : g_qn_v;
    const float*  xn   = (PATH == 0) ? g_xn_m : g_xn_v;
    const __half* LamT = (PATH == 0) ? g_LamTm : g_LamTv;

    const int tid = threadIdx.x, wid = tid >> 5, lane = tid & 31;
    const int q0 = blockIdx.x * QT;
    const int i0 = blockIdx.y * ICHUNK;

    for (int t = tid; t < QT * SEGS; t += 256) {
        const int r = t / SEGS, s = t % SEGS;
        *(uint4*)&Qs[r * LDA + s * 8] = *(const uint4*)(Qh + (q0 + r) * DK + s * 8);
    }
    if (tid < QT) qns[tid] = qn[q0 + tid];

    float Cz[4][4];
    #pragma unroll
    for (int j = 0; j < 4; ++j)
        #pragma unroll
        for (int k = 0; k < 4; ++k) Cz[j][k] = 0.0f;

    for (int it = 0; it < ICHUNK / IT; ++it) {
        const int ib = i0 + it * IT;
        __syncthreads();
        for (int t = tid; t < IT * SEGS; t += 256) {
            const int r = t / SEGS, s = t % SEGS;
            *(uint4*)&Xs[r * LDA + s * 8] = *(const uint4*)(Xh + (ib + r) * DK + s * 8);
        }
        {
            const int r = tid >> 3, s = tid & 7;
            *(uint4*)&Ls[r * LDL + s * 8] = *(const uint4*)(LamT + r * N_XR + ib + s * 8);
        }
        if (tid < IT) xns[tid] = xn[ib + tid];
        __syncthreads();

        // ---- GEMM1: S[16 x 64] = Q_tile @ X_tile^T
        float S[8][4];
        #pragma unroll
        for (int nb = 0; nb < 8; ++nb)
            #pragma unroll
            for (int k = 0; k < 4; ++k) S[nb][k] = 0.0f;

        #pragma unroll
        for (int ks = 0; ks < DK / 16; ++ks) {
            uint32_t a[4];
            const __half* ap = &Qs[(wid * 16 + (lane >> 2)) * LDA + ks * 16 + (lane & 3) * 2];
            a[0] = *(const uint32_t*)ap;
            a[1] = *(const uint32_t*)(ap + 8 * LDA);
            a[2] = *(const uint32_t*)(ap + 8);
            a[3] = *(const uint32_t*)(ap + 8 * LDA + 8);
            #pragma unroll
            for (int nb = 0; nb < 8; ++nb) {
                uint32_t b[2];
                const __half* bp = &Xs[(nb * 8 + (lane >> 2)) * LDA + ks * 16 + (lane & 3) * 2];
                b[0] = *(const uint32_t*)bp;
                b[1] = *(const uint32_t*)(bp + 8);
                mma16816(S[nb], a, b);
            }
        }

        // ---- epilogue: P = exp(min(2S - qn - xn, 0)/128), repacked as A-frags
        const float q0n = qns[wid * 16 + (lane >> 2)];
        const float q1n = qns[wid * 16 + (lane >> 2) + 8];
        uint32_t Pa[8][2];
        #pragma unroll
        for (int nb = 0; nb < 8; ++nb) {
            const float x0 = xns[nb * 8 + (lane & 3) * 2];
            const float x1 = xns[nb * 8 + (lane & 3) * 2 + 1];
            const float t00 = fminf(fmaf(2.0f, S[nb][0], -(q0n + x0)), 0.0f) * INV_2L2;
            const float t01 = fminf(fmaf(2.0f, S[nb][1], -(q0n + x1)), 0.0f) * INV_2L2;
            const float t10 = fminf(fmaf(2.0f, S[nb][2], -(q1n + x0)), 0.0f) * INV_2L2;
            const float t11 = fminf(fmaf(2.0f, S[nb][3], -(q1n + x1)), 0.0f) * INV_2L2;
            __half2 p0 = __floats2half2_rn(__expf(t00), __expf(t01));
            __half2 p1 = __floats2half2_rn(__expf(t10), __expf(t11));
            Pa[nb][0] = *reinterpret_cast<const uint32_t*>(&p0);
            Pa[nb][1] = *reinterpret_cast<const uint32_t*>(&p1);
        }

        // ---- GEMM2: Cz[16 x 32] += P[16 x 64] @ Lam_tile[64 x 32]
        #pragma unroll
        for (int kc = 0; kc < 4; ++kc) {
            uint32_t a[4] = {Pa[2 * kc][0], Pa[2 * kc][1],
                             Pa[2 * kc + 1][0], Pa[2 * kc + 1][1]};
            #pragma unroll
            for (int jb = 0; jb < 4; ++jb) {
                uint32_t b[2];
                const __half* bp = &Ls[(jb * 8 + (lane >> 2)) * LDL + kc * 16 + (lane & 3) * 2];
                b[0] = *(const uint32_t*)bp;
                b[1] = *(const uint32_t*)(bp + 8);
                mma16816(Cz[jb], a, b);
            }
        }
    }

    const int r = q0 + wid * 16 + (lane >> 2);
    const int c = (lane & 3) * 2;
    #pragma unroll
    for (int jb = 0; jb < 4; ++jb) {
        atomicAdd(&out[r * 32 + jb * 8 + c],           Cz[jb][0]);
        atomicAdd(&out[r * 32 + jb * 8 + c + 1],       Cz[jb][1]);
        atomicAdd(&out[(r + 8) * 32 + jb * 8 + c],     Cz[jb][2]);
        atomicAdd(&out[(r + 8) * 32 + jb * 8 + c + 1], Cz[jb][3]);
    }
}

// ------------------------- launch --------------------------------------------
extern "C" void kernel_launch(void* const* d_in, const int* in_sizes, int n_in,
                              void* d_out, int out_size) {
    (void)in_sizes; (void)n_in; (void)out_size;
    const float* x_mu   = (const float*)d_in[0];
    const float* y_eta  = (const float*)d_in[1];
    const float* y_mean = (const float*)d_in[2];
    const float* y_var  = (const float*)d_in[3];
    const float* X_mean = (const float*)d_in[4];
    const float* X_var  = (const float*)d_in[5];
    const float* Z_mean = (const float*)d_in[6];
    const float* Z_var  = (const float*)d_in[7];
    const float* kXXm   = (const float*)d_in[8];
    const float* kXXv   = (const float*)d_in[9];
    float* out = (float*)d_out;

    prep_kernel<<<N_Q / 8, 256>>>(x_mu, y_eta, y_mean, y_var,
                                  X_mean, X_var, Z_mean, Z_var, out);

    dim3 lgrid(N_XR / 128, 4);
    lambda_kernel<0><<<lgrid, 256>>>(kXXm);
    lambda_kernel<1><<<lgrid, 256>>>(kXXv);

    lamconvert_kernel<<<(N_XR * D_OUT) / 256, 256>>>();

    dim3 tgrid(N_Q / 128, 4);
    transport_kernel<0><<<tgrid, 256>>>(out);
    transport_kernel<1><<<tgrid, 256>>>(out);
}

// round 2
// speedup vs baseline: 1.3137x; 1.3137x over previous
#include <cuda_runtime.h>
#include <cuda_fp16.h>
#include <cstdint>

// ---------------------------------------------------------------------------
// CondTransport: out = (y_mean + y_var) + z_mean + z_var
//   z = rbf(X, x, l=8).T @ (kXX_inv @ Z)   for mean (DK=64) and var (DK=96)
// fp16 mma.sync m16n8k16, fp32 accum, flash-style fusion.
// R2: reg-double-buffered pipelines, scale-folded epilogue (ex2), coalesced
//     lambda transpose, fused lambda launch.
// ---------------------------------------------------------------------------

namespace {
constexpr int N_Q     = 8192;
constexpr int N_XR    = 8192;
constexpr int D_OUT   = 32;
constexpr int DK_MEAN = 64;
constexpr int DK_VAR  = 96;
constexpr float VAR_EPS_F = 0.01f;
}

// ------------------------- device scratch (no allocs allowed) ---------------
__device__ __half g_Qm[N_Q * DK_MEAN];
__device__ __half g_Qv[N_Q * DK_VAR];
__device__ __half g_Xm[N_XR * DK_MEAN];
__device__ __half g_Xv[N_XR * DK_VAR];
__device__ float  g_qn_m[N_Q];    // NEGATED scaled squared norms
__device__ float  g_qn_v[N_Q];
__device__ float  g_xn_m[N_XR];
__device__ float  g_xn_v[N_XR];
__device__ __half g_ZTm[D_OUT * N_XR];    // Z transposed [32][8192], fp16
__device__ __half g_ZTv[D_OUT * N_XR];
__device__ float  g_LamFm[N_XR * D_OUT];  // fp32 Lambda accumulators
__device__ float  g_LamFv[N_XR * D_OUT];
__device__ __half g_LamTm[D_OUT * N_XR];  // Lambda transposed [32][8192], fp16
__device__ __half g_LamTv[D_OUT * N_XR];

// ------------------------- helpers ------------------------------------------
__device__ __forceinline__ void mma16816(float c[4], const uint32_t a[4],
                                         const uint32_t b[2]) {
    asm volatile(
        "mma.sync.aligned.m16n8k16.row.col.f32.f16.f16.f32 "
        "{%0,%1,%2,%3}, {%4,%5,%6,%7}, {%8,%9}, {%0,%1,%2,%3};\n"
        : "+f"(c[0]), "+f"(c[1]), "+f"(c[2]), "+f"(c[3])
        : "r"(a[0]), "r"(a[1]), "r"(a[2]), "r"(a[3]), "r"(b[0]), "r"(b[1]));
}

__device__ __forceinline__ float ex2f(float x) {
    float y;
    asm("ex2.approx.ftz.f32 %0, %1;" : "=f"(y) : "f"(x));
    return y;
}

// ------------------------- prep ---------------------------------------------
// One warp per row. Features prescaled by a = sqrt(log2e / (2 l^2)) so the
// transport epilogue is exp2(2S' - qn' - xn') with no per-element scaling.
// Norms are stored NEGATED. Also builds transposed fp16 Z, zeroes LamF,
// inits out = y_mean + y_var.
__global__ void prep_kernel(const float* __restrict__ x_mu,
                            const float* __restrict__ y_eta,
                            const float* __restrict__ y_mean,
                            const float* __restrict__ y_var,
                            const float* __restrict__ X_mean,
                            const float* __restrict__ X_var,
                            const float* __restrict__ Z_mean,
                            const float* __restrict__ Z_var,
                            float* __restrict__ out) {
    const int row  = blockIdx.x * 8 + (threadIdx.x >> 5);
    const int lane = threadIdx.x & 31;
    const float A = sqrtf(1.4426950408889634f / 128.0f);   // sqrt(log2e/(2 l^2))

    // ---- query-side features: x_mean = [x_mu, ymv], x_var = [x_mu, ef, ymv]
    const float ymv_raw = y_mean[row * 32 + lane] + y_var[row * 32 + lane];
    const float xm  = A * x_mu[row * 32 + lane];
    const float ymv = A * ymv_raw;
    const float ef  = A * VAR_EPS_F * y_eta[(N_Q - 1 - row) * 32 + lane];  // flip

    g_Qm[row * DK_MEAN + lane]       = __float2half(xm);
    g_Qm[row * DK_MEAN + 32 + lane]  = __float2half(ymv);
    g_Qv[row * DK_VAR + lane]        = __float2half(xm);
    g_Qv[row * DK_VAR + 32 + lane]   = __float2half(ef);
    g_Qv[row * DK_VAR + 64 + lane]   = __float2half(ymv);
    out[row * 32 + lane] = ymv_raw;

    float nm = xm * xm + ymv * ymv;
    float nv = nm + ef * ef;

    // ---- X-side features + norms (same prescale)
    const float a0 = A * X_mean[row * 64 + lane];
    const float a1 = A * X_mean[row * 64 + 32 + lane];
    g_Xm[row * 64 + lane]      = __float2half(a0);
    g_Xm[row * 64 + 32 + lane] = __float2half(a1);
    float xnm = a0 * a0 + a1 * a1;

    const float b0 = A * X_var[row * 96 + lane];
    const float b1 = A * X_var[row * 96 + 32 + lane];
    const float b2 = A * X_var[row * 96 + 64 + lane];
    g_Xv[row * 96 + lane]      = __float2half(b0);
    g_Xv[row * 96 + 32 + lane] = __float2half(b1);
    g_Xv[row * 96 + 64 + lane] = __float2half(b2);
    float xnv = b0 * b0 + b1 * b1 + b2 * b2;

    #pragma unroll
    for (int o = 16; o; o >>= 1) {
        nm  += __shfl_xor_sync(0xffffffffu, nm, o);
        nv  += __shfl_xor_sync(0xffffffffu, nv, o);
        xnm += __shfl_xor_sync(0xffffffffu, xnm, o);
        xnv += __shfl_xor_sync(0xffffffffu, xnv, o);
    }
    if (lane == 0) {
        g_qn_m[row] = -nm;
        g_qn_v[row] = -nv;
        g_xn_m[row] = -xnm;
        g_xn_v[row] = -xnv;
    }

    // ---- Z transposed fp16, Lambda accumulators zeroed
    g_ZTm[lane * N_XR + row] = __float2half(Z_mean[row * 32 + lane]);
    g_ZTv[lane * N_XR + row] = __float2half(Z_var[row * 32 + lane]);
    g_LamFm[row * 32 + lane] = 0.0f;
    g_LamFv[row * 32 + lane] = 0.0f;
}

// ------------------------- Lambda = kXX_inv @ Z ------------------------------
// M-tile 128 (8 warps x m16), N=32, K split 4-way (blockIdx.y), both paths in
// one launch (blockIdx.z). Register-double-buffered mainloop: prefetch next
// fp32 A tile + fp16 Z tile into registers while mma consumes current smem.
__global__ void __launch_bounds__(256, 2)
lambda_kernel(const float* __restrict__ Am, const float* __restrict__ Av) {
    constexpr int KT = 64;
    constexpr int KCHUNK = N_XR / 4;
    constexpr int NIT = KCHUNK / KT;
    __shared__ __half As[128 * 72];
    __shared__ __half Zs[32 * 72];

    const int path = blockIdx.z;
    const float* A    = path ? Av : Am;
    const __half* ZT  = path ? g_ZTv : g_ZTm;
    float* LamF       = path ? g_LamFv : g_LamFm;

    const int tid = threadIdx.x, wid = tid >> 5, lane = tid & 31;
    const int m0 = blockIdx.x * 128;
    const int k0 = blockIdx.y * KCHUNK;

    float C[4][4];
    #pragma unroll
    for (int j = 0; j < 4; ++j)
        #pragma unroll
        for (int k = 0; k < 4; ++k) C[j][k] = 0.0f;

    float4 ar[8];
    uint4  zr;
    const int zrow = tid >> 3, zcol = tid & 7;

    auto load_tile = [&](int kb) {
        #pragma unroll
        for (int p = 0; p < 8; ++p) {
            const int idx = tid + p * 256;
            const int r = idx >> 4, s = idx & 15;
            ar[p] = *(const float4*)(A + (size_t)(m0 + r) * N_XR + kb + s * 4);
        }
        zr = *(const uint4*)(ZT + zrow * N_XR + kb + zcol * 8);
    };

    load_tile(k0);

    for (int kt = 0; kt < NIT; ++kt) {
        // store prefetched regs into smem (convert fp32->fp16)
        #pragma unroll
        for (int p = 0; p < 8; ++p) {
            const int idx = tid + p * 256;
            const int r = idx >> 4, s = idx & 15;
            *(__half2*)&As[r * 72 + s * 4]     = __floats2half2_rn(ar[p].x, ar[p].y);
            *(__half2*)&As[r * 72 + s * 4 + 2] = __floats2half2_rn(ar[p].z, ar[p].w);
        }
        *(uint4*)&Zs[zrow * 72 + zcol * 8] = zr;
        __syncthreads();

        if (kt + 1 < NIT) load_tile(k0 + (kt + 1) * KT);   // LDGs in flight

        #pragma unroll
        for (int ks = 0; ks < 4; ++ks) {
            uint32_t a[4];
            const __half* ap = &As[(wid * 16 + (lane >> 2)) * 72 + ks * 16 + (lane & 3) * 2];
            a[0] = *(const uint32_t*)ap;
            a[1] = *(const uint32_t*)(ap + 8 * 72);
            a[2] = *(const uint32_t*)(ap + 8);
            a[3] = *(const uint32_t*)(ap + 8 * 72 + 8);
            #pragma unroll
            for (int jb = 0; jb < 4; ++jb) {
                uint32_t b[2];
                const __half* bp = &Zs[(jb * 8 + (lane >> 2)) * 72 + ks * 16 + (lane & 3) * 2];
                b[0] = *(const uint32_t*)bp;
                b[1] = *(const uint32_t*)(bp + 8);
                mma16816(C[jb], a, b);
            }
        }
        __syncthreads();
    }

    const int r = m0 + wid * 16 + (lane >> 2);
    const int c = (lane & 3) * 2;
    #pragma unroll
    for (int jb = 0; jb < 4; ++jb) {
        atomicAdd(&LamF[r * 32 + jb * 8 + c],           C[jb][0]);
        atomicAdd(&LamF[r * 32 + jb * 8 + c + 1],       C[jb][1]);
        atomicAdd(&LamF[(r + 8) * 32 + jb * 8 + c],     C[jb][2]);
        atomicAdd(&LamF[(r + 8) * 32 + jb * 8 + c + 1], C[jb][3]);
    }
}

// ------------------------- Lambda fp32 -> fp16 transposed (coalesced) --------
// Block handles 64 i-rows x 32 j-cols via smem transpose; writes to g_LamT are
// 128B-contiguous per 64-thread group. blockIdx.y selects the path.
__global__ void lamconvert_kernel() {
    __shared__ float s[64][33];
    const float* F = blockIdx.y ? g_LamFv : g_LamFm;
    __half* T      = blockIdx.y ? g_LamTv : g_LamTm;
    const int i0 = blockIdx.x * 64;
    const int tid = threadIdx.x;
    #pragma unroll
    for (int idx = tid; idx < 2048; idx += 256) {
        const int i = idx >> 5, j = idx & 31;
        s[i][j] = F[(i0 + i) * 32 + j];
    }
    __syncthreads();
    #pragma unroll
    for (int idx = tid; idx < 2048; idx += 256) {
        const int j = idx >> 6, i = idx & 63;
        T[j * N_XR + i0 + i] = __float2half(s[i][j]);
    }
}

// ------------------------- fused transport -----------------------------------
// out[q,:] += sum_i exp2(2<x_q',X_i'> - qn' - xn') * Lam[i,:]  (primes = scaled)
// Q-tile 128 (8 warps x m16), i-tile 64, i-range split 4-way (blockIdx.y),
// register-double-buffered mainloop, atomicAdd into out.
template <int PATH>
__global__ void __launch_bounds__(256, 2)
transport_kernel(float* __restrict__ out) {
    constexpr int DK  = (PATH == 0) ? DK_MEAN : DK_VAR;
    constexpr int QT  = 128;
    constexpr int IT  = 64;
    constexpr int LDA = DK + 8;
    constexpr int LDL = IT + 8;
    constexpr int ICHUNK = N_XR / 4;
    constexpr int NIT = ICHUNK / IT;
    constexpr int SEGS = DK / 8;           // uint4 segments per row
    constexpr int NX4  = IT * SEGS / 256;  // X-tile uint4 per thread (2 or 3)

    __shared__ __half Qs[QT * LDA];
    __shared__ __half Xs[IT * LDA];
    __shared__ __half Ls[D_OUT * LDL];
    __shared__ float  qns[QT];
    __shared__ float  xns[IT];

    const __half* Qh   = (PATH == 0) ? g_Qm : g_Qv;
    const __half* Xh   = (PATH == 0) ? g_Xm : g_Xv;
    const float*  qn   = (PATH == 0) ? g_qn_m : g_qn_v;   // negated
    const float*  xn   = (PATH == 0) ? g_xn_m : g_xn_v;   // negated
    const __half* LamT = (PATH == 0) ? g_LamTm : g_LamTv;

    const int tid = threadIdx.x, wid = tid >> 5, lane = tid & 31;
    const int q0 = blockIdx.x * QT;
    const int i0 = blockIdx.y * ICHUNK;

    for (int t = tid; t < QT * SEGS; t += 256) {
        const int r = t / SEGS, s = t % SEGS;
        *(uint4*)&Qs[r * LDA + s * 8] = *(const uint4*)(Qh + (q0 + r) * DK + s * 8);
    }
    if (tid < QT) qns[tid] = qn[q0 + tid];

    float Cz[4][4];
    #pragma unroll
    for (int j = 0; j < 4; ++j)
        #pragma unroll
        for (int k = 0; k < 4; ++k) Cz[j][k] = 0.0f;

    uint4 xr[NX4];
    uint4 lr;
    float xnr = 0.0f;
    const int lrow = tid >> 3, lcol = tid & 7;

    auto load_tile = [&](int ib) {
        #pragma unroll
        for (int p = 0; p < NX4; ++p) {
            const int idx = tid + p * 256;
            const int r = idx / SEGS, s = idx % SEGS;
            xr[p] = *(const uint4*)(Xh + (ib + r) * DK + s * 8);
        }
        lr = *(const uint4*)(LamT + lrow * N_XR + ib + lcol * 8);
        if (tid < IT) xnr = xn[ib + tid];
    };

    load_tile(i0);

    for (int it = 0; it < NIT; ++it) {
        #pragma unroll
        for (int p = 0; p < NX4; ++p) {
            const int idx = tid + p * 256;
            const int r = idx / SEGS, s = idx % SEGS;
            *(uint4*)&Xs[r * LDA + s * 8] = xr[p];
        }
        *(uint4*)&Ls[lrow * LDL + lcol * 8] = lr;
        if (tid < IT) xns[tid] = xnr;
        __syncthreads();

        if (it + 1 < NIT) load_tile(i0 + (it + 1) * IT);   // LDGs in flight

        // ---- GEMM1: S[16 x 64] = Q_tile @ X_tile^T  (scaled features)
        float S[8][4];
        #pragma unroll
        for (int nb = 0; nb < 8; ++nb)
            #pragma unroll
            for (int k = 0; k < 4; ++k) S[nb][k] = 0.0f;

        #pragma unroll
        for (int ks = 0; ks < DK / 16; ++ks) {
            uint32_t a[4];
            const __half* ap = &Qs[(wid * 16 + (lane >> 2)) * LDA + ks * 16 + (lane & 3) * 2];
            a[0] = *(const uint32_t*)ap;
            a[1] = *(const uint32_t*)(ap + 8 * LDA);
            a[2] = *(const uint32_t*)(ap + 8);
            a[3] = *(const uint32_t*)(ap + 8 * LDA + 8);
            #pragma unroll
            for (int nb = 0; nb < 8; ++nb) {
                uint32_t b[2];
                const __half* bp = &Xs[(nb * 8 + (lane >> 2)) * LDA + ks * 16 + (lane & 3) * 2];
                b[0] = *(const uint32_t*)bp;
                b[1] = *(const uint32_t*)(bp + 8);
                mma16816(S[nb], a, b);
            }
        }

        // ---- epilogue: P = exp2(min(2S + nq + nx, 0)), repacked as A-frags
        const float nq0 = qns[wid * 16 + (lane >> 2)];
        const float nq1 = qns[wid * 16 + (lane >> 2) + 8];
        uint32_t Pa[8][2];
        #pragma unroll
        for (int nb = 0; nb < 8; ++nb) {
            const float nx0 = xns[nb * 8 + (lane & 3) * 2];
            const float nx1 = xns[nb * 8 + (lane & 3) * 2 + 1];
            const float t00 = fminf(fmaf(2.0f, S[nb][0], nq0 + nx0), 0.0f);
            const float t01 = fminf(fmaf(2.0f, S[nb][1], nq0 + nx1), 0.0f);
            const float t10 = fminf(fmaf(2.0f, S[nb][2], nq1 + nx0), 0.0f);
            const float t11 = fminf(fmaf(2.0f, S[nb][3], nq1 + nx1), 0.0f);
            __half2 p0 = __floats2half2_rn(ex2f(t00), ex2f(t01));
            __half2 p1 = __floats2half2_rn(ex2f(t10), ex2f(t11));
            Pa[nb][0] = *reinterpret_cast<const uint32_t*>(&p0);
            Pa[nb][1] = *reinterpret_cast<const uint32_t*>(&p1);
        }

        // ---- GEMM2: Cz[16 x 32] += P[16 x 64] @ Lam_tile[64 x 32]
        #pragma unroll
        for (int kc = 0; kc < 4; ++kc) {
            uint32_t a[4] = {Pa[2 * kc][0], Pa[2 * kc][1],
                             Pa[2 * kc + 1][0], Pa[2 * kc + 1][1]};
            #pragma unroll
            for (int jb = 0; jb < 4; ++jb) {
                uint32_t b[2];
                const __half* bp = &Ls[(jb * 8 + (lane >> 2)) * LDL + kc * 16 + (lane & 3) * 2];
                b[0] = *(const uint32_t*)bp;
                b[1] = *(const uint32_t*)(bp + 8);
                mma16816(Cz[jb], a, b);
            }
        }
        __syncthreads();
    }

    const int r = q0 + wid * 16 + (lane >> 2);
    const int c = (lane & 3) * 2;
    #pragma unroll
    for (int jb = 0; jb < 4; ++jb) {
        atomicAdd(&out[r * 32 + jb * 8 + c],           Cz[jb][0]);
        atomicAdd(&out[r * 32 + jb * 8 + c + 1],       Cz[jb][1]);
        atomicAdd(&out[(r + 8) * 32 + jb * 8 + c],     Cz[jb][2]);
        atomicAdd(&out[(r + 8) * 32 + jb * 8 + c + 1], Cz[jb][3]);
    }
}

// ------------------------- launch --------------------------------------------
extern "C" void kernel_launch(void* const* d_in, const int* in_sizes, int n_in,
                              void* d_out, int out_size) {
    (void)in_sizes; (void)n_in; (void)out_size;
    const float* x_mu   = (const float*)d_in[0];
    const float* y_eta  = (const float*)d_in[1];
    const float* y_mean = (const float*)d_in[2];
    const float* y_var  = (const float*)d_in[3];
    const float* X_mean = (const float*)d_in[4];
    const float* X_var  = (const float*)d_in[5];
    const float* Z_mean = (const float*)d_in[6];
    const float* Z_var  = (const float*)d_in[7];
    const float* kXXm   = (const float*)d_in[8];
    const float* kXXv   = (const float*)d_in[9];
    float* out = (float*)d_out;

    prep_kernel<<<N_Q / 8, 256>>>(x_mu, y_eta, y_mean, y_var,
                                  X_mean, X_var, Z_mean, Z_var, out);

    dim3 lgrid(N_XR / 128, 4, 2);
    lambda_kernel<<<lgrid, 256>>>(kXXm, kXXv);

    dim3 cgrid(N_XR / 64, 2);
    lamconvert_kernel<<<cgrid, 256>>>();

    dim3 tgrid(N_Q / 128, 4);
    transport_kernel<0><<<tgrid, 256>>>(out);
    transport_kernel<1><<<tgrid, 256>>>(out);
}

// round 10
// speedup vs baseline: 1.4128x; 1.0754x over previous
#include <cuda_runtime.h>
#include <cuda_fp16.h>
#include <cstdint>

// ---------------------------------------------------------------------------
// CondTransport: out = (y_mean + y_var) + z_mean + z_var
//   z = rbf(X, x, l=8).T @ (kXX_inv @ Z)   for mean (DK=64) and var (DK=96)
// fp16 mma.sync m16n8k16, fp32 accum, flash-style fusion.
// R3 transport: hoisted Q fragments, ldmatrix.x4, fused mean+var launch.
// R9 lambda: double-buffered smem tiles, single barrier per K-iter.
// ---------------------------------------------------------------------------

namespace {
constexpr int N_Q     = 8192;
constexpr int N_XR    = 8192;
constexpr int D_OUT   = 32;
constexpr int DK_MEAN = 64;
constexpr int DK_VAR  = 96;
constexpr float VAR_EPS_F = 0.01f;
}

// ------------------------- device scratch (no allocs allowed) ---------------
__device__ __half g_Qm[N_Q * DK_MEAN];
__device__ __half g_Qv[N_Q * DK_VAR];
__device__ __half g_Xm[N_XR * DK_MEAN];
__device__ __half g_Xv[N_XR * DK_VAR];
__device__ float  g_qn_m[N_Q];    // NEGATED scaled squared norms
__device__ float  g_qn_v[N_Q];
__device__ float  g_xn_m[N_XR];
__device__ float  g_xn_v[N_XR];
__device__ __half g_ZTm[D_OUT * N_XR];    // Z transposed [32][8192], fp16
__device__ __half g_ZTv[D_OUT * N_XR];
__device__ float  g_LamFm[N_XR * D_OUT];  // fp32 Lambda accumulators
__device__ float  g_LamFv[N_XR * D_OUT];
__device__ __half g_LamTm[D_OUT * N_XR];  // Lambda transposed [32][8192], fp16
__device__ __half g_LamTv[D_OUT * N_XR];

// ------------------------- helpers ------------------------------------------
__device__ __forceinline__ void mma16816(float c[4], const uint32_t a[4],
                                         const uint32_t b0, const uint32_t b1) {
    asm volatile(
        "mma.sync.aligned.m16n8k16.row.col.f32.f16.f16.f32 "
        "{%0,%1,%2,%3}, {%4,%5,%6,%7}, {%8,%9}, {%0,%1,%2,%3};\n"
        : "+f"(c[0]), "+f"(c[1]), "+f"(c[2]), "+f"(c[3])
        : "r"(a[0]), "r"(a[1]), "r"(a[2]), "r"(a[3]), "r"(b0), "r"(b1));
}

__device__ __forceinline__ void ldsm4(uint32_t r[4], uint32_t saddr) {
    asm volatile(
        "ldmatrix.sync.aligned.m8n8.x4.shared.b16 {%0,%1,%2,%3}, [%4];"
        : "=r"(r[0]), "=r"(r[1]), "=r"(r[2]), "=r"(r[3])
        : "r"(saddr));
}

__device__ __forceinline__ float ex2f(float x) {
    float y;
    asm("ex2.approx.ftz.f32 %0, %1;" : "=f"(y) : "f"(x));
    return y;
}

__device__ __forceinline__ uint32_t smem_u32(const void* p) {
    return (uint32_t)__cvta_generic_to_shared(p);
}

// ------------------------- prep ---------------------------------------------
// One warp per row. Features prescaled by a = sqrt(log2e / (2 l^2)) so the
// transport epilogue is exp2(2S' - qn' - xn') with no per-element scaling.
// Norms stored NEGATED. Builds transposed fp16 Z, zeroes LamF, out=y_mean+y_var.
__global__ void prep_kernel(const float* __restrict__ x_mu,
                            const float* __restrict__ y_eta,
                            const float* __restrict__ y_mean,
                            const float* __restrict__ y_var,
                            const float* __restrict__ X_mean,
                            const float* __restrict__ X_var,
                            const float* __restrict__ Z_mean,
                            const float* __restrict__ Z_var,
                            float* __restrict__ out) {
    const int row  = blockIdx.x * 8 + (threadIdx.x >> 5);
    const int lane = threadIdx.x & 31;
    const float A = sqrtf(1.4426950408889634f / 128.0f);   // sqrt(log2e/(2 l^2))

    const float ymv_raw = y_mean[row * 32 + lane] + y_var[row * 32 + lane];
    const float xm  = A * x_mu[row * 32 + lane];
    const float ymv = A * ymv_raw;
    const float ef  = A * VAR_EPS_F * y_eta[(N_Q - 1 - row) * 32 + lane];  // flip

    g_Qm[row * DK_MEAN + lane]       = __float2half(xm);
    g_Qm[row * DK_MEAN + 32 + lane]  = __float2half(ymv);
    g_Qv[row * DK_VAR + lane]        = __float2half(xm);
    g_Qv[row * DK_VAR + 32 + lane]   = __float2half(ef);
    g_Qv[row * DK_VAR + 64 + lane]   = __float2half(ymv);
    out[row * 32 + lane] = ymv_raw;

    float nm = xm * xm + ymv * ymv;
    float nv = nm + ef * ef;

    const float a0 = A * X_mean[row * 64 + lane];
    const float a1 = A * X_mean[row * 64 + 32 + lane];
    g_Xm[row * 64 + lane]      = __float2half(a0);
    g_Xm[row * 64 + 32 + lane] = __float2half(a1);
    float xnm = a0 * a0 + a1 * a1;

    const float b0 = A * X_var[row * 96 + lane];
    const float b1 = A * X_var[row * 96 + 32 + lane];
    const float b2 = A * X_var[row * 96 + 64 + lane];
    g_Xv[row * 96 + lane]      = __float2half(b0);
    g_Xv[row * 96 + 32 + lane] = __float2half(b1);
    g_Xv[row * 96 + 64 + lane] = __float2half(b2);
    float xnv = b0 * b0 + b1 * b1 + b2 * b2;

    #pragma unroll
    for (int o = 16; o; o >>= 1) {
        nm  += __shfl_xor_sync(0xffffffffu, nm, o);
        nv  += __shfl_xor_sync(0xffffffffu, nv, o);
        xnm += __shfl_xor_sync(0xffffffffu, xnm, o);
        xnv += __shfl_xor_sync(0xffffffffu, xnv, o);
    }
    if (lane == 0) {
        g_qn_m[row] = -nm;
        g_qn_v[row] = -nv;
        g_xn_m[row] = -xnm;
        g_xn_v[row] = -xnv;
    }

    g_ZTm[lane * N_XR + row] = __float2half(Z_mean[row * 32 + lane]);
    g_ZTv[lane * N_XR + row] = __float2half(Z_var[row * 32 + lane]);
    g_LamFm[row * 32 + lane] = 0.0f;
    g_LamFv[row * 32 + lane] = 0.0f;
}

// ------------------------- Lambda = kXX_inv @ Z ------------------------------
// M-tile 128 (8 warps x m16), N=32, K split 4-way (blockIdx.y), both paths in
// one launch (blockIdx.z). R9: DOUBLE-BUFFERED smem tiles — one barrier per
// K-iter (after stores); mma on buf b overlaps the next iter's stores to b^1.
// Safety: a warp in iter k+1 stores buf (k+1)&1 while laggards in iter k read
// buf k&1 — disjoint; the post-store barrier bounds the skew to one iter.
__global__ void __launch_bounds__(256, 2)
lambda_kernel(const float* __restrict__ Am, const float* __restrict__ Av) {
    constexpr int KT = 64;
    constexpr int KCHUNK = N_XR / 4;
    constexpr int NIT = KCHUNK / KT;
    __shared__ __half As[2][128 * 72];   // 2 x 18 KB
    __shared__ __half Zs[2][32 * 72];    // 2 x 4.5 KB  (total 45 KB < 48 KB)

    const int path = blockIdx.z;
    const float* A    = path ? Av : Am;
    const __half* ZT  = path ? g_ZTv : g_ZTm;
    float* LamF       = path ? g_LamFv : g_LamFm;

    const int tid = threadIdx.x, wid = tid >> 5, lane = tid & 31;
    const int m0 = blockIdx.x * 128;
    const int k0 = blockIdx.y * KCHUNK;

    float C[4][4];
    #pragma unroll
    for (int j = 0; j < 4; ++j)
        #pragma unroll
        for (int k = 0; k < 4; ++k) C[j][k] = 0.0f;

    float4 ar[8];
    uint4  zr;
    const int zrow = tid >> 3, zcol = tid & 7;

    auto load_tile = [&](int kb) {
        #pragma unroll
        for (int p = 0; p < 8; ++p) {
            const int idx = tid + p * 256;
            const int r = idx >> 4, s = idx & 15;
            ar[p] = *(const float4*)(A + (size_t)(m0 + r) * N_XR + kb + s * 4);
        }
        zr = *(const uint4*)(ZT + zrow * N_XR + kb + zcol * 8);
    };

    load_tile(k0);

    for (int kt = 0; kt < NIT; ++kt) {
        const int b = kt & 1;
        // store prefetched regs into smem buf b (convert fp32->fp16)
        #pragma unroll
        for (int p = 0; p < 8; ++p) {
            const int idx = tid + p * 256;
            const int r = idx >> 4, s = idx & 15;
            *(__half2*)&As[b][r * 72 + s * 4]     = __floats2half2_rn(ar[p].x, ar[p].y);
            *(__half2*)&As[b][r * 72 + s * 4 + 2] = __floats2half2_rn(ar[p].z, ar[p].w);
        }
        *(uint4*)&Zs[b][zrow * 72 + zcol * 8] = zr;
        __syncthreads();

        if (kt + 1 < NIT) load_tile(k0 + (kt + 1) * KT);   // LDGs in flight

        #pragma unroll
        for (int ks = 0; ks < 4; ++ks) {
            uint32_t a[4];
            const __half* ap = &As[b][(wid * 16 + (lane >> 2)) * 72 + ks * 16 + (lane & 3) * 2];
            a[0] = *(const uint32_t*)ap;
            a[1] = *(const uint32_t*)(ap + 8 * 72);
            a[2] = *(const uint32_t*)(ap + 8);
            a[3] = *(const uint32_t*)(ap + 8 * 72 + 8);
            #pragma unroll
            for (int jb = 0; jb < 4; ++jb) {
                const __half* bp = &Zs[b][(jb * 8 + (lane >> 2)) * 72 + ks * 16 + (lane & 3) * 2];
                mma16816(C[jb], a, *(const uint32_t*)bp, *(const uint32_t*)(bp + 8));
            }
        }
        // no trailing barrier: next iter writes the OTHER buffer
    }

    const int r = m0 + wid * 16 + (lane >> 2);
    const int c = (lane & 3) * 2;
    #pragma unroll
    for (int jb = 0; jb < 4; ++jb) {
        atomicAdd(&LamF[r * 32 + jb * 8 + c],           C[jb][0]);
        atomicAdd(&LamF[r * 32 + jb * 8 + c + 1],       C[jb][1]);
        atomicAdd(&LamF[(r + 8) * 32 + jb * 8 + c],     C[jb][2]);
        atomicAdd(&LamF[(r + 8) * 32 + jb * 8 + c + 1], C[jb][3]);
    }
}

// ------------------------- Lambda fp32 -> fp16 transposed (coalesced) --------
__global__ void lamconvert_kernel() {
    __shared__ float s[64][33];
    const float* F = blockIdx.y ? g_LamFv : g_LamFm;
    __half* T      = blockIdx.y ? g_LamTv : g_LamTm;
    const int i0 = blockIdx.x * 64;
    const int tid = threadIdx.x;
    #pragma unroll
    for (int idx = tid; idx < 2048; idx += 256) {
        const int i = idx >> 5, j = idx & 31;
        s[i][j] = F[(i0 + i) * 32 + j];
    }
    __syncthreads();
    #pragma unroll
    for (int idx = tid; idx < 2048; idx += 256) {
        const int j = idx >> 6, i = idx & 63;
        T[j * N_XR + i0 + i] = __float2half(s[i][j]);
    }
}

// ------------------------- fused transport -----------------------------------
// out[q,:] += sum_i exp2(2<x_q',X_i'> - qn' - xn') * Lam[i,:]
// Q-tile 128 (8 warps x m16), i-tile 64, i-range split 4-way (blockIdx.y),
// both paths in one launch (blockIdx.z). Q fragments hoisted to registers,
// X/Lam fragments via ldmatrix.x4, reg-double-buffered mainloop.
constexpr int T_LDA = DK_VAR + 8;   // 104: row stride for Qs/Xs (both paths)
constexpr int T_LDL = 64 + 8;       // 72: row stride for Ls

template <int DK>
__device__ __forceinline__ void transport_body(
    const __half* __restrict__ Qh, const __half* __restrict__ Xh,
    const float* __restrict__ qn, const float* __restrict__ xn,
    const __half* __restrict__ LamT, float* __restrict__ out,
    __half* Qs, __half* Xs, __half* Ls, float* qns, float* xns) {
    constexpr int QT  = 128;
    constexpr int IT  = 64;
    constexpr int ICHUNK = N_XR / 4;
    constexpr int NIT = ICHUNK / IT;
    constexpr int SEGS = DK / 8;           // uint4 segments per row
    constexpr int NX4  = IT * SEGS / 256;  // X-tile uint4 per thread (2 or 3)
    constexpr int NKS  = DK / 16;

    const int tid = threadIdx.x, wid = tid >> 5, lane = tid & 31;
    const int q0 = blockIdx.x * QT;
    const int i0 = blockIdx.y * ICHUNK;

    // ---- load Q tile + norms into smem
    for (int t = tid; t < QT * SEGS; t += 256) {
        const int r = t / SEGS, s = t % SEGS;
        *(uint4*)&Qs[r * T_LDA + s * 8] = *(const uint4*)(Qh + (q0 + r) * DK + s * 8);
    }
    if (tid < QT) qns[tid] = qn[q0 + tid];
    __syncthreads();

    // ---- hoist Q fragments (loop-invariant) via ldmatrix
    const int g = lane >> 3, r8 = lane & 7;
    const uint32_t qs_b = smem_u32(Qs);
    const uint32_t xs_b = smem_u32(Xs);
    const uint32_t ls_b = smem_u32(Ls);

    uint32_t qf[NKS][4];
    #pragma unroll
    for (int ks = 0; ks < NKS; ++ks) {
        const uint32_t addr = qs_b +
            ((wid * 16 + (g & 1) * 8 + r8) * T_LDA + ks * 16 + (g >> 1) * 8) * 2;
        ldsm4(qf[ks], addr);
    }

    float Cz[4][4];
    #pragma unroll
    for (int j = 0; j < 4; ++j)
        #pragma unroll
        for (int k = 0; k < 4; ++k) Cz[j][k] = 0.0f;

    uint4 xr[NX4];
    uint4 lr;
    float xnr = 0.0f;
    const int lrow = tid >> 3, lcol = tid & 7;

    auto load_tile = [&](int ib) {
        #pragma unroll
        for (int p = 0; p < NX4; ++p) {
            const int idx = tid + p * 256;
            const int r = idx / SEGS, s = idx % SEGS;
            xr[p] = *(const uint4*)(Xh + (ib + r) * DK + s * 8);
        }
        lr = *(const uint4*)(LamT + lrow * N_XR + ib + lcol * 8);
        if (tid < IT) xnr = xn[ib + tid];
    };

    load_tile(i0);

    // per-lane ldmatrix base offsets (bytes) for X / Lam
    const uint32_t x_lane_off = (((g >> 1) * 8 + r8) * T_LDA + (g & 1) * 8) * 2;
    const uint32_t l_lane_off = (((g >> 1) * 8 + r8) * T_LDL + (g & 1) * 8) * 2;

    for (int it = 0; it < NIT; ++it) {
        #pragma unroll
        for (int p = 0; p < NX4; ++p) {
            const int idx = tid + p * 256;
            const int r = idx / SEGS, s = idx % SEGS;
            *(uint4*)&Xs[r * T_LDA + s * 8] = xr[p];
        }
        *(uint4*)&Ls[lrow * T_LDL + lcol * 8] = lr;
        if (tid < IT) xns[tid] = xnr;
        __syncthreads();

        if (it + 1 < NIT) load_tile(i0 + (it + 1) * IT);   // LDGs in flight

        // ---- GEMM1: S[16 x 64] = Q_tile @ X_tile^T
        float S[8][4];
        #pragma unroll
        for (int nb = 0; nb < 8; ++nb)
            #pragma unroll
            for (int k = 0; k < 4; ++k) S[nb][k] = 0.0f;

        #pragma unroll
        for (int ks = 0; ks < NKS; ++ks) {
            #pragma unroll
            for (int p = 0; p < 4; ++p) {   // nb pairs
                uint32_t bf[4];
                ldsm4(bf, xs_b + x_lane_off + (p * 16 * T_LDA + ks * 16) * 2);
                mma16816(S[2 * p],     qf[ks], bf[0], bf[1]);
                mma16816(S[2 * p + 1], qf[ks], bf[2], bf[3]);
            }
        }

        // ---- epilogue: P = exp2(min(2S + nq + nx, 0)), repacked as A-frags
        const float nq0 = qns[wid * 16 + (lane >> 2)];
        const float nq1 = qns[wid * 16 + (lane >> 2) + 8];
        uint32_t Pa[8][2];
        #pragma unroll
        for (int nb = 0; nb < 8; ++nb) {
            const float2 nx2 = *(const float2*)&xns[nb * 8 + (lane & 3) * 2];
            const float t00 = fminf(fmaf(2.0f, S[nb][0], nq0 + nx2.x), 0.0f);
            const float t01 = fminf(fmaf(2.0f, S[nb][1], nq0 + nx2.y), 0.0f);
            const float t10 = fminf(fmaf(2.0f, S[nb][2], nq1 + nx2.x), 0.0f);
            const float t11 = fminf(fmaf(2.0f, S[nb][3], nq1 + nx2.y), 0.0f);
            __half2 p0 = __floats2half2_rn(ex2f(t00), ex2f(t01));
            __half2 p1 = __floats2half2_rn(ex2f(t10), ex2f(t11));
            Pa[nb][0] = *reinterpret_cast<const uint32_t*>(&p0);
            Pa[nb][1] = *reinterpret_cast<const uint32_t*>(&p1);
        }

        // ---- GEMM2: Cz[16 x 32] += P[16 x 64] @ Lam_tile[64 x 32]
        #pragma unroll
        for (int kc = 0; kc < 4; ++kc) {
            uint32_t a[4] = {Pa[2 * kc][0], Pa[2 * kc][1],
                             Pa[2 * kc + 1][0], Pa[2 * kc + 1][1]};
            #pragma unroll
            for (int p = 0; p < 2; ++p) {   // jb pairs
                uint32_t bf[4];
                ldsm4(bf, ls_b + l_lane_off + (p * 16 * T_LDL + kc * 16) * 2);
                mma16816(Cz[2 * p],     a, bf[0], bf[1]);
                mma16816(Cz[2 * p + 1], a, bf[2], bf[3]);
            }
        }
        __syncthreads();
    }

    const int r = q0 + wid * 16 + (lane >> 2);
    const int c = (lane & 3) * 2;
    #pragma unroll
    for (int jb = 0; jb < 4; ++jb) {
        atomicAdd(&out[r * 32 + jb * 8 + c],           Cz[jb][0]);
        atomicAdd(&out[r * 32 + jb * 8 + c + 1],       Cz[jb][1]);
        atomicAdd(&out[(r + 8) * 32 + jb * 8 + c],     Cz[jb][2]);
        atomicAdd(&out[(r + 8) * 32 + jb * 8 + c + 1], Cz[jb][3]);
    }
}

__global__ void __launch_bounds__(256, 2)
transport_kernel(float* __restrict__ out) {
    __shared__ __half Qs[128 * T_LDA];
    __shared__ __half Xs[64 * T_LDA];
    __shared__ __half Ls[32 * T_LDL];
    __shared__ float  qns[128];
    __shared__ float  xns[64];

    if (blockIdx.z == 0) {
        transport_body<DK_MEAN>(g_Qm, g_Xm, g_qn_m, g_xn_m, g_LamTm, out,
                                Qs, Xs, Ls, qns, xns);
    } else {
        transport_body<DK_VAR>(g_Qv, g_Xv, g_qn_v, g_xn_v, g_LamTv, out,
                               Qs, Xs, Ls, qns, xns);
    }
}

// ------------------------- launch --------------------------------------------
extern "C" void kernel_launch(void* const* d_in, const int* in_sizes, int n_in,
                              void* d_out, int out_size) {
    (void)in_sizes; (void)n_in; (void)out_size;
    const float* x_mu   = (const float*)d_in[0];
    const float* y_eta  = (const float*)d_in[1];
    const float* y_mean = (const float*)d_in[2];
    const float* y_var  = (const float*)d_in[3];
    const float* X_mean = (const float*)d_in[4];
    const float* X_var  = (const float*)d_in[5];
    const float* Z_mean = (const float*)d_in[6];
    const float* Z_var  = (const float*)d_in[7];
    const float* kXXm   = (const float*)d_in[8];
    const float* kXXv   = (const float*)d_in[9];
    float* out = (float*)d_out;

    prep_kernel<<<N_Q / 8, 256>>>(x_mu, y_eta, y_mean, y_var,
                                  X_mean, X_var, Z_mean, Z_var, out);

    dim3 lgrid(N_XR / 128, 4, 2);
    lambda_kernel<<<lgrid, 256>>>(kXXm, kXXv);

    dim3 cgrid(N_XR / 64, 2);
    lamconvert_kernel<<<cgrid, 256>>>();

    dim3 tgrid(N_Q / 128, 4, 2);
    transport_kernel<<<tgrid, 256>>>(out);
}

// round 17
// speedup vs baseline: 1.4213x; 1.0061x over previous
#include <cuda_runtime.h>
#include <cuda_fp16.h>
#include <cstdint>

// ---------------------------------------------------------------------------
// CondTransport: out = (y_mean + y_var) + z_mean + z_var
//   z = rbf(X, x, l=8).T @ (kXX_inv @ Z)   for mean (DK=64) and var (DK=96)
// fp16 mma.sync m16n8k16, fp32 accum, flash-style fusion.
// R10 transport: 4 warps x m32 warp-tiles — each B-fragment ldsm feeds 4 MMAs,
//   halving smem bytes/FLOP (was at the 0.0625 B/FLOP smem-BW roofline).
// R9 lambda: double-buffered smem tiles.  (Re-run #6: infra timeouts.)
// ---------------------------------------------------------------------------

namespace {
constexpr int N_Q     = 8192;
constexpr int N_XR    = 8192;
constexpr int D_OUT   = 32;
constexpr int DK_MEAN = 64;
constexpr int DK_VAR  = 96;
constexpr float VAR_EPS_F = 0.01f;
}

// ------------------------- device scratch (no allocs allowed) ---------------
__device__ __half g_Qm[N_Q * DK_MEAN];
__device__ __half g_Qv[N_Q * DK_VAR];
__device__ __half g_Xm[N_XR * DK_MEAN];
__device__ __half g_Xv[N_XR * DK_VAR];
__device__ float  g_qn_m[N_Q];    // NEGATED scaled squared norms
__device__ float  g_qn_v[N_Q];
__device__ float  g_xn_m[N_XR];
__device__ float  g_xn_v[N_XR];
__device__ __half g_ZTm[D_OUT * N_XR];    // Z transposed [32][8192], fp16
__device__ __half g_ZTv[D_OUT * N_XR];
__device__ float  g_LamFm[N_XR * D_OUT];  // fp32 Lambda accumulators
__device__ float  g_LamFv[N_XR * D_OUT];
__device__ __half g_LamTm[D_OUT * N_XR];  // Lambda transposed [32][8192], fp16
__device__ __half g_LamTv[D_OUT * N_XR];

// ------------------------- helpers ------------------------------------------
__device__ __forceinline__ void mma16816(float c[4], const uint32_t a[4],
                                         const uint32_t b0, const uint32_t b1) {
    asm volatile(
        "mma.sync.aligned.m16n8k16.row.col.f32.f16.f16.f32 "
        "{%0,%1,%2,%3}, {%4,%5,%6,%7}, {%8,%9}, {%0,%1,%2,%3};\n"
        : "+f"(c[0]), "+f"(c[1]), "+f"(c[2]), "+f"(c[3])
        : "r"(a[0]), "r"(a[1]), "r"(a[2]), "r"(a[3]), "r"(b0), "r"(b1));
}

__device__ __forceinline__ void ldsm4(uint32_t r[4], uint32_t saddr) {
    asm volatile(
        "ldmatrix.sync.aligned.m8n8.x4.shared.b16 {%0,%1,%2,%3}, [%4];"
        : "=r"(r[0]), "=r"(r[1]), "=r"(r[2]), "=r"(r[3])
        : "r"(saddr));
}

__device__ __forceinline__ float ex2f(float x) {
    float y;
    asm("ex2.approx.ftz.f32 %0, %1;" : "=f"(y) : "f"(x));
    return y;
}

__device__ __forceinline__ uint32_t smem_u32(const void* p) {
    return (uint32_t)__cvta_generic_to_shared(p);
}

// ------------------------- prep ---------------------------------------------
__global__ void prep_kernel(const float* __restrict__ x_mu,
                            const float* __restrict__ y_eta,
                            const float* __restrict__ y_mean,
                            const float* __restrict__ y_var,
                            const float* __restrict__ X_mean,
                            const float* __restrict__ X_var,
                            const float* __restrict__ Z_mean,
                            const float* __restrict__ Z_var,
                            float* __restrict__ out) {
    const int row  = blockIdx.x * 8 + (threadIdx.x >> 5);
    const int lane = threadIdx.x & 31;
    const float A = sqrtf(1.4426950408889634f / 128.0f);   // sqrt(log2e/(2 l^2))

    const float ymv_raw = y_mean[row * 32 + lane] + y_var[row * 32 + lane];
    const float xm  = A * x_mu[row * 32 + lane];
    const float ymv = A * ymv_raw;
    const float ef  = A * VAR_EPS_F * y_eta[(N_Q - 1 - row) * 32 + lane];  // flip

    g_Qm[row * DK_MEAN + lane]       = __float2half(xm);
    g_Qm[row * DK_MEAN + 32 + lane]  = __float2half(ymv);
    g_Qv[row * DK_VAR + lane]        = __float2half(xm);
    g_Qv[row * DK_VAR + 32 + lane]   = __float2half(ef);
    g_Qv[row * DK_VAR + 64 + lane]   = __float2half(ymv);
    out[row * 32 + lane] = ymv_raw;

    float nm = xm * xm + ymv * ymv;
    float nv = nm + ef * ef;

    const float a0 = A * X_mean[row * 64 + lane];
    const float a1 = A * X_mean[row * 64 + 32 + lane];
    g_Xm[row * 64 + lane]      = __float2half(a0);
    g_Xm[row * 64 + 32 + lane] = __float2half(a1);
    float xnm = a0 * a0 + a1 * a1;

    const float b0 = A * X_var[row * 96 + lane];
    const float b1 = A * X_var[row * 96 + 32 + lane];
    const float b2 = A * X_var[row * 96 + 64 + lane];
    g_Xv[row * 96 + lane]      = __float2half(b0);
    g_Xv[row * 96 + 32 + lane] = __float2half(b1);
    g_Xv[row * 96 + 64 + lane] = __float2half(b2);
    float xnv = b0 * b0 + b1 * b1 + b2 * b2;

    #pragma unroll
    for (int o = 16; o; o >>= 1) {
        nm  += __shfl_xor_sync(0xffffffffu, nm, o);
        nv  += __shfl_xor_sync(0xffffffffu, nv, o);
        xnm += __shfl_xor_sync(0xffffffffu, xnm, o);
        xnv += __shfl_xor_sync(0xffffffffu, xnv, o);
    }
    if (lane == 0) {
        g_qn_m[row] = -nm;
        g_qn_v[row] = -nv;
        g_xn_m[row] = -xnm;
        g_xn_v[row] = -xnv;
    }

    g_ZTm[lane * N_XR + row] = __float2half(Z_mean[row * 32 + lane]);
    g_ZTv[lane * N_XR + row] = __float2half(Z_var[row * 32 + lane]);
    g_LamFm[row * 32 + lane] = 0.0f;
    g_LamFv[row * 32 + lane] = 0.0f;
}

// ------------------------- Lambda = kXX_inv @ Z ------------------------------
// R9: double-buffered smem tiles, single barrier per K-iter.
__global__ void __launch_bounds__(256, 2)
lambda_kernel(const float* __restrict__ Am, const float* __restrict__ Av) {
    constexpr int KT = 64;
    constexpr int KCHUNK = N_XR / 4;
    constexpr int NIT = KCHUNK / KT;
    __shared__ __half As[2][128 * 72];
    __shared__ __half Zs[2][32 * 72];

    const int path = blockIdx.z;
    const float* A    = path ? Av : Am;
    const __half* ZT  = path ? g_ZTv : g_ZTm;
    float* LamF       = path ? g_LamFv : g_LamFm;

    const int tid = threadIdx.x, wid = tid >> 5, lane = tid & 31;
    const int m0 = blockIdx.x * 128;
    const int k0 = blockIdx.y * KCHUNK;

    float C[4][4];
    #pragma unroll
    for (int j = 0; j < 4; ++j)
        #pragma unroll
        for (int k = 0; k < 4; ++k) C[j][k] = 0.0f;

    float4 ar[8];
    uint4  zr;
    const int zrow = tid >> 3, zcol = tid & 7;

    auto load_tile = [&](int kb) {
        #pragma unroll
        for (int p = 0; p < 8; ++p) {
            const int idx = tid + p * 256;
            const int r = idx >> 4, s = idx & 15;
            ar[p] = *(const float4*)(A + (size_t)(m0 + r) * N_XR + kb + s * 4);
        }
        zr = *(const uint4*)(ZT + zrow * N_XR + kb + zcol * 8);
    };

    load_tile(k0);

    for (int kt = 0; kt < NIT; ++kt) {
        const int b = kt & 1;
        #pragma unroll
        for (int p = 0; p < 8; ++p) {
            const int idx = tid + p * 256;
            const int r = idx >> 4, s = idx & 15;
            *(__half2*)&As[b][r * 72 + s * 4]     = __floats2half2_rn(ar[p].x, ar[p].y);
            *(__half2*)&As[b][r * 72 + s * 4 + 2] = __floats2half2_rn(ar[p].z, ar[p].w);
        }
        *(uint4*)&Zs[b][zrow * 72 + zcol * 8] = zr;
        __syncthreads();

        if (kt + 1 < NIT) load_tile(k0 + (kt + 1) * KT);

        #pragma unroll
        for (int ks = 0; ks < 4; ++ks) {
            uint32_t a[4];
            const __half* ap = &As[b][(wid * 16 + (lane >> 2)) * 72 + ks * 16 + (lane & 3) * 2];
            a[0] = *(const uint32_t*)ap;
            a[1] = *(const uint32_t*)(ap + 8 * 72);
            a[2] = *(const uint32_t*)(ap + 8);
            a[3] = *(const uint32_t*)(ap + 8 * 72 + 8);
            #pragma unroll
            for (int jb = 0; jb < 4; ++jb) {
                const __half* bp = &Zs[b][(jb * 8 + (lane >> 2)) * 72 + ks * 16 + (lane & 3) * 2];
                mma16816(C[jb], a, *(const uint32_t*)bp, *(const uint32_t*)(bp + 8));
            }
        }
    }

    const int r = m0 + wid * 16 + (lane >> 2);
    const int c = (lane & 3) * 2;
    #pragma unroll
    for (int jb = 0; jb < 4; ++jb) {
        atomicAdd(&LamF[r * 32 + jb * 8 + c],           C[jb][0]);
        atomicAdd(&LamF[r * 32 + jb * 8 + c + 1],       C[jb][1]);
        atomicAdd(&LamF[(r + 8) * 32 + jb * 8 + c],     C[jb][2]);
        atomicAdd(&LamF[(r + 8) * 32 + jb * 8 + c + 1], C[jb][3]);
    }
}

// ------------------------- Lambda fp32 -> fp16 transposed (coalesced) --------
__global__ void lamconvert_kernel() {
    __shared__ float s[64][33];
    const float* F = blockIdx.y ? g_LamFv : g_LamFm;
    __half* T      = blockIdx.y ? g_LamTv : g_LamTm;
    const int i0 = blockIdx.x * 64;
    const int tid = threadIdx.x;
    #pragma unroll
    for (int idx = tid; idx < 2048; idx += 256) {
        const int i = idx >> 5, j = idx & 31;
        s[i][j] = F[(i0 + i) * 32 + j];
    }
    __syncthreads();
    #pragma unroll
    for (int idx = tid; idx < 2048; idx += 256) {
        const int j = idx >> 6, i = idx & 63;
        T[j * N_XR + i0 + i] = __float2half(s[i][j]);
    }
}

// ------------------------- fused transport -----------------------------------
// R10: 128 threads (4 warps), warp m-tile = 32 rows (two m16 halves).
// Each B-fragment ldsm4 feeds 4 MMAs; smem bytes/FLOP halved.
constexpr int T_LDA = DK_VAR + 8;   // 104: row stride for Qs/Xs (both paths)
constexpr int T_LDL = 64 + 8;       // 72: row stride for Ls
constexpr int T_THREADS = 128;

template <int DK>
__device__ __forceinline__ void transport_body(
    const __half* __restrict__ Qh, const __half* __restrict__ Xh,
    const float* __restrict__ qn, const float* __restrict__ xn,
    const __half* __restrict__ LamT, float* __restrict__ out,
    __half* Qs, __half* Xs, __half* Ls, float* qns, float* xns) {
    constexpr int QT  = 128;
    constexpr int IT  = 64;
    constexpr int ICHUNK = N_XR / 4;
    constexpr int NIT = ICHUNK / IT;
    constexpr int SEGS = DK / 8;                 // uint4 segments per row
    constexpr int NX4  = IT * SEGS / T_THREADS;  // 4 (mean) or 6 (var)
    constexpr int NKS  = DK / 16;

    const int tid = threadIdx.x, wid = tid >> 5, lane = tid & 31;
    const int q0 = blockIdx.x * QT;
    const int i0 = blockIdx.y * ICHUNK;

    // ---- load Q tile + norms into smem
    for (int t = tid; t < QT * SEGS; t += T_THREADS) {
        const int r = t / SEGS, s = t % SEGS;
        *(uint4*)&Qs[r * T_LDA + s * 8] = *(const uint4*)(Qh + (q0 + r) * DK + s * 8);
    }
    qns[tid] = qn[q0 + tid];   // tid covers all 128 = QT
    __syncthreads();

    // ---- hoist Q fragments for BOTH m16 halves (loop-invariant)
    const int g = lane >> 3, r8 = lane & 7;
    const uint32_t qs_b = smem_u32(Qs);
    const uint32_t xs_b = smem_u32(Xs);
    const uint32_t ls_b = smem_u32(Ls);

    uint32_t qf[2][NKS][4];
    #pragma unroll
    for (int h = 0; h < 2; ++h)
        #pragma unroll
        for (int ks = 0; ks < NKS; ++ks) {
            const uint32_t addr = qs_b +
                ((wid * 32 + h * 16 + (g & 1) * 8 + r8) * T_LDA + ks * 16 + (g >> 1) * 8) * 2;
            ldsm4(qf[h][ks], addr);
        }

    float Cz[2][4][4];
    #pragma unroll
    for (int h = 0; h < 2; ++h)
        #pragma unroll
        for (int j = 0; j < 4; ++j)
            #pragma unroll
            for (int k = 0; k < 4; ++k) Cz[h][j][k] = 0.0f;

    uint4 xr[NX4];
    uint4 lr[2];
    float xnr = 0.0f;

    auto load_tile = [&](int ib) {
        #pragma unroll
        for (int p = 0; p < NX4; ++p) {
            const int idx = tid + p * T_THREADS;
            const int r = idx / SEGS, s = idx % SEGS;
            xr[p] = *(const uint4*)(Xh + (ib + r) * DK + s * 8);
        }
        #pragma unroll
        for (int p = 0; p < 2; ++p) {
            const int idx = tid + p * T_THREADS;
            lr[p] = *(const uint4*)(LamT + (idx >> 3) * N_XR + ib + (idx & 7) * 8);
        }
        if (tid < IT) xnr = xn[ib + tid];
    };

    load_tile(i0);

    const uint32_t x_lane_off = (((g >> 1) * 8 + r8) * T_LDA + (g & 1) * 8) * 2;
    const uint32_t l_lane_off = (((g >> 1) * 8 + r8) * T_LDL + (g & 1) * 8) * 2;

    for (int it = 0; it < NIT; ++it) {
        #pragma unroll
        for (int p = 0; p < NX4; ++p) {
            const int idx = tid + p * T_THREADS;
            const int r = idx / SEGS, s = idx % SEGS;
            *(uint4*)&Xs[r * T_LDA + s * 8] = xr[p];
        }
        #pragma unroll
        for (int p = 0; p < 2; ++p) {
            const int idx = tid + p * T_THREADS;
            *(uint4*)&Ls[(idx >> 3) * T_LDL + (idx & 7) * 8] = lr[p];
        }
        if (tid < IT) xns[tid] = xnr;
        __syncthreads();

        if (it + 1 < NIT) load_tile(i0 + (it + 1) * IT);   // LDGs in flight

        // ---- GEMM1: S[32 x 64] = Q_tile(m32) @ X_tile^T, one bf -> 4 MMAs
        float S[2][8][4];
        #pragma unroll
        for (int h = 0; h < 2; ++h)
            #pragma unroll
            for (int nb = 0; nb < 8; ++nb)
                #pragma unroll
                for (int k = 0; k < 4; ++k) S[h][nb][k] = 0.0f;

        #pragma unroll
        for (int ks = 0; ks < NKS; ++ks) {
            #pragma unroll
            for (int p = 0; p < 4; ++p) {   // nb pairs
                uint32_t bf[4];
                ldsm4(bf, xs_b + x_lane_off + (p * 16 * T_LDA + ks * 16) * 2);
                mma16816(S[0][2 * p],     qf[0][ks], bf[0], bf[1]);
                mma16816(S[0][2 * p + 1], qf[0][ks], bf[2], bf[3]);
                mma16816(S[1][2 * p],     qf[1][ks], bf[0], bf[1]);
                mma16816(S[1][2 * p + 1], qf[1][ks], bf[2], bf[3]);
            }
        }

        // ---- epilogue: P = exp2(min(2S + nq + nx, 0)), repacked as A-frags
        uint32_t Pa[2][8][2];
        #pragma unroll
        for (int h = 0; h < 2; ++h) {
            const float nq0 = qns[wid * 32 + h * 16 + (lane >> 2)];
            const float nq1 = qns[wid * 32 + h * 16 + (lane >> 2) + 8];
            #pragma unroll
            for (int nb = 0; nb < 8; ++nb) {
                const float2 nx2 = *(const float2*)&xns[nb * 8 + (lane & 3) * 2];
                const float t00 = fminf(fmaf(2.0f, S[h][nb][0], nq0 + nx2.x), 0.0f);
                const float t01 = fminf(fmaf(2.0f, S[h][nb][1], nq0 + nx2.y), 0.0f);
                const float t10 = fminf(fmaf(2.0f, S[h][nb][2], nq1 + nx2.x), 0.0f);
                const float t11 = fminf(fmaf(2.0f, S[h][nb][3], nq1 + nx2.y), 0.0f);
                __half2 p0 = __floats2half2_rn(ex2f(t00), ex2f(t01));
                __half2 p1 = __floats2half2_rn(ex2f(t10), ex2f(t11));
                Pa[h][nb][0] = *reinterpret_cast<const uint32_t*>(&p0);
                Pa[h][nb][1] = *reinterpret_cast<const uint32_t*>(&p1);
            }
        }

        // ---- GEMM2: Cz[32 x 32] += P[32 x 64] @ Lam_tile[64 x 32], lf -> 4 MMAs
        #pragma unroll
        for (int kc = 0; kc < 4; ++kc) {
            uint32_t a0[4] = {Pa[0][2 * kc][0], Pa[0][2 * kc][1],
                              Pa[0][2 * kc + 1][0], Pa[0][2 * kc + 1][1]};
            uint32_t a1[4] = {Pa[1][2 * kc][0], Pa[1][2 * kc][1],
                              Pa[1][2 * kc + 1][0], Pa[1][2 * kc + 1][1]};
            #pragma unroll
            for (int p = 0; p < 2; ++p) {   // jb pairs
                uint32_t lf[4];
                ldsm4(lf, ls_b + l_lane_off + (p * 16 * T_LDL + kc * 16) * 2);
                mma16816(Cz[0][2 * p],     a0, lf[0], lf[1]);
                mma16816(Cz[0][2 * p + 1], a0, lf[2], lf[3]);
                mma16816(Cz[1][2 * p],     a1, lf[0], lf[1]);
                mma16816(Cz[1][2 * p + 1], a1, lf[2], lf[3]);
            }
        }
        __syncthreads();
    }

    const int c = (lane & 3) * 2;
    #pragma unroll
    for (int h = 0; h < 2; ++h) {
        const int r = q0 + wid * 32 + h * 16 + (lane >> 2);
        #pragma unroll
        for (int jb = 0; jb < 4; ++jb) {
            atomicAdd(&out[r * 32 + jb * 8 + c],           Cz[h][jb][0]);
            atomicAdd(&out[r * 32 + jb * 8 + c + 1],       Cz[h][jb][1]);
            atomicAdd(&out[(r + 8) * 32 + jb * 8 + c],     Cz[h][jb][2]);
            atomicAdd(&out[(r + 8) * 32 + jb * 8 + c + 1], Cz[h][jb][3]);
        }
    }
}

__global__ void __launch_bounds__(T_THREADS, 2)
transport_kernel(float* __restrict__ out) {
    __shared__ __half Qs[128 * T_LDA];
    __shared__ __half Xs[64 * T_LDA];
    __shared__ __half Ls[32 * T_LDL];
    __shared__ float  qns[128];
    __shared__ float  xns[64];

    if (blockIdx.z == 0) {
        transport_body<DK_MEAN>(g_Qm, g_Xm, g_qn_m, g_xn_m, g_LamTm, out,
                                Qs, Xs, Ls, qns, xns);
    } else {
        transport_body<DK_VAR>(g_Qv, g_Xv, g_qn_v, g_xn_v, g_LamTv, out,
                               Qs, Xs, Ls, qns, xns);
    }
}

// ------------------------- launch --------------------------------------------
extern "C" void kernel_launch(void* const* d_in, const int* in_sizes, int n_in,
                              void* d_out, int out_size) {
    (void)in_sizes; (void)n_in; (void)out_size;
    const float* x_mu   = (const float*)d_in[0];
    const float* y_eta  = (const float*)d_in[1];
    const float* y_mean = (const float*)d_in[2];
    const float* y_var  = (const float*)d_in[3];
    const float* X_mean = (const float*)d_in[4];
    const float* X_var  = (const float*)d_in[5];
    const float* Z_mean = (const float*)d_in[6];
    const float* Z_var  = (const float*)d_in[7];
    const float* kXXm   = (const float*)d_in[8];
    const float* kXXv   = (const float*)d_in[9];
    float* out = (float*)d_out;

    prep_kernel<<<N_Q / 8, 256>>>(x_mu, y_eta, y_mean, y_var,
                                  X_mean, X_var, Z_mean, Z_var, out);

    dim3 lgrid(N_XR / 128, 4, 2);
    lambda_kernel<<<lgrid, 256>>>(kXXm, kXXv);

    dim3 cgrid(N_XR / 64, 2);
    lamconvert_kernel<<<cgrid, 256>>>();

    dim3 tgrid(N_Q / 128, 4, 2);
    transport_kernel<<<tgrid, T_THREADS>>>(out);
}